// round 1
// baseline (speedup 1.0000x reference)
#include <cuda_runtime.h>
#include <math.h>

#define GROUPS 4
#define DIM    512
#define NSAMP  16384
#define EPS    1e-5f

// ---------------- scratch (static device globals; no allocation) ----------------
__device__ float g_colsum_part[GROUPS][32][DIM];
__device__ float g_mu[GROUPS][DIM];
__device__ float g_S [GROUPS][DIM * DIM];
__device__ float g_Ba[GROUPS][DIM * DIM];
__device__ float g_Bb[GROUPS][DIM * DIM];
__device__ float g_T1[GROUPS][DIM * DIM];
__device__ float g_T2[GROUPS][DIM * DIM];
__device__ float g_normpart[GROUPS][64];
__device__ float g_scale[GROUPS][2];   // [0] = 1/||S||_F  (for S),  [1] = 1/sqrt(||S||_F) (for W)

// ---------------- 1. column sums (deterministic partials) ----------------
// grid (32 row-chunks, GROUPS), block 512: thread c sums 512 rows of column c.
__global__ void colsum_kernel(const float* __restrict__ Z) {
    int g = blockIdx.y, chunk = blockIdx.x, c = threadIdx.x;
    const float* Zg = Z + (size_t)g * NSAMP * DIM;
    size_t base = (size_t)chunk * 512 * DIM + c;
    float s = 0.f;
    #pragma unroll 4
    for (int r = 0; r < 512; r++) s += Zg[base + (size_t)r * DIM];
    g_colsum_part[g][chunk][c] = s;
}

// grid (GROUPS), block 512
__global__ void mu_kernel() {
    int g = blockIdx.x, c = threadIdx.x;
    float s = 0.f;
    #pragma unroll
    for (int ch = 0; ch < 32; ch++) s += g_colsum_part[g][ch][c];
    g_mu[g][c] = s * (1.0f / NSAMP);
}

// ---------------- 2. Gram: G = Z^T Z (upper-triangular tiles + mirror) ----------------
// grid (8, 8, GROUPS), block 256; 64x64 output tile, 4x4 per thread, K(=n)=16384.
__global__ void __launch_bounds__(256) gram_kernel(const float* __restrict__ Zall) {
    if (blockIdx.x < blockIdx.y) return;          // upper triangle only
    int g = blockIdx.z;
    const float* Z = Zall + (size_t)g * NSAMP * DIM;
    float* Sg = g_S[g];
    int d0 = blockIdx.y * 64, e0 = blockIdx.x * 64;

    __shared__ float As[16][64];
    __shared__ float Bs[16][64];
    int tid = threadIdx.x;
    int tx = tid & 15, ty = tid >> 4;
    float acc[4][4] = {};

    for (int n0 = 0; n0 < NSAMP; n0 += 16) {
        #pragma unroll
        for (int l = 0; l < 4; l++) {
            int nn = (tid >> 6) + l * 4;
            int dd = tid & 63;
            size_t row = (size_t)(n0 + nn) * DIM;
            As[nn][dd] = Z[row + d0 + dd];
            Bs[nn][dd] = Z[row + e0 + dd];
        }
        __syncthreads();
        #pragma unroll
        for (int nn = 0; nn < 16; nn++) {
            float4 a4 = *(const float4*)&As[nn][ty * 4];
            float4 b4 = *(const float4*)&Bs[nn][tx * 4];
            float a[4] = {a4.x, a4.y, a4.z, a4.w};
            float b[4] = {b4.x, b4.y, b4.z, b4.w};
            #pragma unroll
            for (int ii = 0; ii < 4; ii++)
                #pragma unroll
                for (int jj = 0; jj < 4; jj++)
                    acc[ii][jj] += a[ii] * b[jj];
        }
        __syncthreads();
    }
    #pragma unroll
    for (int ii = 0; ii < 4; ii++) {
        float4 v = make_float4(acc[ii][0], acc[ii][1], acc[ii][2], acc[ii][3]);
        *(float4*)&Sg[(size_t)(d0 + ty * 4 + ii) * DIM + e0 + tx * 4] = v;
    }
    if (blockIdx.x != blockIdx.y) {               // mirror to lower triangle
        #pragma unroll
        for (int ii = 0; ii < 4; ii++)
            #pragma unroll
            for (int jj = 0; jj < 4; jj++)
                Sg[(size_t)(e0 + tx * 4 + jj) * DIM + d0 + ty * 4 + ii] = acc[ii][jj];
    }
}

// ---------------- 3. S = G - N*mu mu^T + eps I, plus Frobenius partials ----------------
// grid (64, GROUPS), block 256
__global__ void sfin_kernel() {
    int g = blockIdx.y, b = blockIdx.x, t = threadIdx.x;
    float ss = 0.f;
    #pragma unroll
    for (int l = 0; l < 16; l++) {
        int idx = b * 4096 + l * 256 + t;
        int d = idx >> 9, e = idx & 511;
        float v = g_S[g][idx] - (float)NSAMP * g_mu[g][d] * g_mu[g][e];
        if (d == e) v += EPS;
        g_S[g][idx] = v;
        ss += v * v;
    }
    __shared__ float red[256];
    red[t] = ss; __syncthreads();
    for (int s2 = 128; s2 > 0; s2 >>= 1) {
        if (t < s2) red[t] += red[t + s2];
        __syncthreads();
    }
    if (t == 0) g_normpart[g][b] = red[0];
}

// grid (GROUPS), block 64
__global__ void norm_kernel() {
    int g = blockIdx.x, t = threadIdx.x;
    __shared__ float red[64];
    red[t] = g_normpart[g][t]; __syncthreads();
    for (int s = 32; s > 0; s >>= 1) {
        if (t < s) red[t] += red[t + s];
        __syncthreads();
    }
    if (t == 0) {
        float nrm = sqrtf(red[0]);
        g_scale[g][0] = 1.0f / nrm;
        g_scale[g][1] = rsqrtf(nrm);
    }
}

// ---------------- 4. S *= 1/||S||;  B1 = 1.5 I - 0.5 S  (first NS iter folded) ----------------
// grid (1024), block 1024
__global__ void nsinit_kernel() {
    int idx = blockIdx.x * 1024 + threadIdx.x;   // 0 .. 4*512*512-1
    int g = idx >> 18;
    int r = idx & 262143;
    int d = r >> 9, e = r & 511;
    float sv = g_S[g][r] * g_scale[g][0];
    g_S[g][r] = sv;
    g_Ba[g][r] = (d == e ? 1.5f : 0.0f) - 0.5f * sv;
}

// ---------------- 5. batched 512x512x512 GEMM (symmetric output: upper + mirror) ----
// C = A*B  row-major; NSMODE=1: C = 1.5*D - 0.5*(A*B)
// grid (8, 8, GROUPS), block 256
template<int NSMODE>
__global__ void __launch_bounds__(256) gemm512_kernel(const float* __restrict__ A,
                                                      const float* __restrict__ Bm,
                                                      const float* __restrict__ D,
                                                      float* __restrict__ C) {
    if (blockIdx.x < blockIdx.y) return;          // output symmetric
    int g = blockIdx.z;
    const float* Ag = A  + (size_t)g * DIM * DIM;
    const float* Bg = Bm + (size_t)g * DIM * DIM;
    float*       Cg = C  + (size_t)g * DIM * DIM;
    int i0 = blockIdx.y * 64, j0 = blockIdx.x * 64;

    __shared__ float Ast[16][68];                 // transposed A tile (k-major)
    __shared__ float Bs [16][64];
    int tid = threadIdx.x;
    int tx = tid & 15, ty = tid >> 4;
    float acc[4][4] = {};

    for (int k0 = 0; k0 < DIM; k0 += 16) {
        #pragma unroll
        for (int l = 0; l < 4; l++) {
            int i  = (tid >> 4) + l * 16;
            int kc = tid & 15;
            Ast[kc][i] = Ag[(size_t)(i0 + i) * DIM + k0 + kc];
        }
        #pragma unroll
        for (int l = 0; l < 4; l++) {
            int kc = (tid >> 6) + l * 4;
            int j  = tid & 63;
            Bs[kc][j] = Bg[(size_t)(k0 + kc) * DIM + j0 + j];
        }
        __syncthreads();
        #pragma unroll
        for (int kc = 0; kc < 16; kc++) {
            float4 a4 = *(const float4*)&Ast[kc][ty * 4];
            float4 b4 = *(const float4*)&Bs [kc][tx * 4];
            float a[4] = {a4.x, a4.y, a4.z, a4.w};
            float b[4] = {b4.x, b4.y, b4.z, b4.w};
            #pragma unroll
            for (int ii = 0; ii < 4; ii++)
                #pragma unroll
                for (int jj = 0; jj < 4; jj++)
                    acc[ii][jj] += a[ii] * b[jj];
        }
        __syncthreads();
    }

    float vals[4][4];
    #pragma unroll
    for (int ii = 0; ii < 4; ii++) {
        int i = i0 + ty * 4 + ii;
        if (NSMODE) {
            float4 d4 = *(const float4*)&D[(size_t)g * DIM * DIM + (size_t)i * DIM + j0 + tx * 4];
            vals[ii][0] = 1.5f * d4.x - 0.5f * acc[ii][0];
            vals[ii][1] = 1.5f * d4.y - 0.5f * acc[ii][1];
            vals[ii][2] = 1.5f * d4.z - 0.5f * acc[ii][2];
            vals[ii][3] = 1.5f * d4.w - 0.5f * acc[ii][3];
        } else {
            vals[ii][0] = acc[ii][0]; vals[ii][1] = acc[ii][1];
            vals[ii][2] = acc[ii][2]; vals[ii][3] = acc[ii][3];
        }
        float4 v = make_float4(vals[ii][0], vals[ii][1], vals[ii][2], vals[ii][3]);
        *(float4*)&Cg[(size_t)i * DIM + j0 + tx * 4] = v;
    }
    if (blockIdx.x != blockIdx.y) {
        #pragma unroll
        for (int ii = 0; ii < 4; ii++)
            #pragma unroll
            for (int jj = 0; jj < 4; jj++)
                Cg[(size_t)(j0 + tx * 4 + jj) * DIM + i0 + ty * 4 + ii] = vals[ii][jj];
    }
}

// ---------------- 6. final: out[n][j] = scl * sum_k (Z[n][k]-mu[k]) * B[j][k] --------
// grid (8, 256, GROUPS), block 256; 64(n) x 64(j) tile, K=512 in chunks of 32.
__global__ void __launch_bounds__(256) final_kernel(const float* __restrict__ Zall,
                                                    const float* __restrict__ Bfin,
                                                    float* __restrict__ outAll) {
    int g = blockIdx.z;
    const float* Z  = Zall + (size_t)g * NSAMP * DIM;
    const float* Bg = Bfin + (size_t)g * DIM * DIM;
    float*       Og = outAll + (size_t)g * NSAMP * DIM;
    int n0 = blockIdx.y * 64, j0 = blockIdx.x * 64;

    __shared__ float Ast[32][68];                 // Zc tile, k-major
    __shared__ float Bst[32][68];                 // B tile, k-major
    int tid = threadIdx.x;
    int tx = tid & 15, ty = tid >> 4;
    float scl = g_scale[g][1];
    float acc[4][4] = {};

    for (int k0 = 0; k0 < DIM; k0 += 32) {
        int kc = tid & 31;
        float muv = g_mu[g][k0 + kc];
        #pragma unroll
        for (int l = 0; l < 8; l++) {
            int i = (tid >> 5) + l * 8;
            Ast[kc][i] = Z [(size_t)(n0 + i) * DIM + k0 + kc] - muv;
            Bst[kc][i] = Bg[(size_t)(j0 + i) * DIM + k0 + kc];
        }
        __syncthreads();
        #pragma unroll
        for (int k = 0; k < 32; k++) {
            float4 a4 = *(const float4*)&Ast[k][ty * 4];
            float4 b4 = *(const float4*)&Bst[k][tx * 4];
            float a[4] = {a4.x, a4.y, a4.z, a4.w};
            float b[4] = {b4.x, b4.y, b4.z, b4.w};
            #pragma unroll
            for (int ii = 0; ii < 4; ii++)
                #pragma unroll
                for (int jj = 0; jj < 4; jj++)
                    acc[ii][jj] += a[ii] * b[jj];
        }
        __syncthreads();
    }
    #pragma unroll
    for (int ii = 0; ii < 4; ii++) {
        int n = n0 + ty * 4 + ii;
        float4 v = make_float4(scl * acc[ii][0], scl * acc[ii][1],
                               scl * acc[ii][2], scl * acc[ii][3]);
        *(float4*)&Og[(size_t)n * DIM + j0 + tx * 4] = v;
    }
}

// ---------------- launch ----------------
extern "C" void kernel_launch(void* const* d_in, const int* in_sizes, int n_in,
                              void* d_out, int out_size) {
    (void)in_sizes; (void)n_in; (void)out_size;
    const float* in = (const float*)d_in[0];
    float* out = (float*)d_out;

    float *S, *Ba, *Bb, *T1, *T2;
    cudaGetSymbolAddress((void**)&S,  g_S);
    cudaGetSymbolAddress((void**)&Ba, g_Ba);
    cudaGetSymbolAddress((void**)&Bb, g_Bb);
    cudaGetSymbolAddress((void**)&T1, g_T1);
    cudaGetSymbolAddress((void**)&T2, g_T2);

    colsum_kernel<<<dim3(32, GROUPS), 512>>>(in);
    mu_kernel<<<GROUPS, 512>>>();
    gram_kernel<<<dim3(8, 8, GROUPS), 256>>>(in);
    sfin_kernel<<<dim3(64, GROUPS), 256>>>();
    norm_kernel<<<GROUPS, 64>>>();
    nsinit_kernel<<<1024, 1024>>>();

    // NS iterations 2..5 (iter 1 folded into nsinit)
    float* cur = Ba;
    float* nxt = Bb;
    for (int it = 0; it < 4; it++) {
        gemm512_kernel<0><<<dim3(8, 8, GROUPS), 256>>>(cur, cur, nullptr, T1); // B^2
        gemm512_kernel<0><<<dim3(8, 8, GROUPS), 256>>>(T1, cur, nullptr, T2);  // B^3
        gemm512_kernel<1><<<dim3(8, 8, GROUPS), 256>>>(T2, S, cur, nxt);       // 1.5B - 0.5 B^3 S
        float* tmp = cur; cur = nxt; nxt = tmp;
    }

    final_kernel<<<dim3(8, 256, GROUPS), 256>>>(in, cur, out);
}

// round 3
// speedup vs baseline: 2.4899x; 2.4899x over previous
#include <cuda_runtime.h>
#include <cuda_bf16.h>
#include <stdint.h>
#include <math.h>

#define GROUPS 4
#define DIM    512
#define NSAMP  16384
#define EPS    1e-5f
#define KSPLIT 8

// ======================= helpers =======================
__device__ __forceinline__ uint32_t smem_to_u32(const void* p) {
    uint32_t a;
    asm("{ .reg .u64 t; cvta.to.shared.u64 t, %1; cvt.u32.u64 %0, t; }" : "=r"(a) : "l"(p));
    return a;
}
#define STS128(r0, r1, r2, r3, a) \
    asm volatile("st.shared.v4.b32 [%0], {%1, %2, %3, %4};" :: "r"(a), "r"(r0), "r"(r1), "r"(r2), "r"(r3) : "memory")
#define LDSM_X4(r0, r1, r2, r3, a) \
    asm volatile("ldmatrix.sync.aligned.m8n8.x4.shared.b16 {%0,%1,%2,%3}, [%4];" \
        : "=r"(r0), "=r"(r1), "=r"(r2), "=r"(r3) : "r"(a))
#define LDSM_X2(r0, r1, a) \
    asm volatile("ldmatrix.sync.aligned.m8n8.x2.shared.b16 {%0,%1}, [%2];" \
        : "=r"(r0), "=r"(r1) : "r"(a))
#define MMA16816(d, a, b) \
    asm volatile("mma.sync.aligned.m16n8k16.row.col.f32.bf16.bf16.f32 " \
        "{%0,%1,%2,%3}, {%4,%5,%6,%7}, {%8,%9}, {%0,%1,%2,%3};" \
        : "+f"((d)[0]), "+f"((d)[1]), "+f"((d)[2]), "+f"((d)[3]) \
        : "r"((a)[0]), "r"((a)[1]), "r"((a)[2]), "r"((a)[3]), "r"((b)[0]), "r"((b)[1]))

// ======================= device scratch =======================
__device__ __align__(16) float g_colsum_part[GROUPS][32][DIM];
__device__ __align__(16) float g_mu[GROUPS][DIM];
__device__ __align__(16) float g_Gpart[KSPLIT][GROUPS][DIM * DIM];
__device__ __align__(16) float g_Sf[GROUPS][DIM * DIM];
__device__ __align__(16) float g_Bf[2][GROUPS][DIM * DIM];
__device__ __align__(16) __nv_bfloat16 g_Sh[GROUPS][DIM * DIM];
__device__ __align__(16) __nv_bfloat16 g_Sl[GROUPS][DIM * DIM];
__device__ __align__(16) __nv_bfloat16 g_Bh[2][GROUPS][DIM * DIM];
__device__ __align__(16) __nv_bfloat16 g_Bl[2][GROUPS][DIM * DIM];
__device__ __align__(16) __nv_bfloat16 g_T1h[GROUPS][DIM * DIM];
__device__ __align__(16) __nv_bfloat16 g_T1l[GROUPS][DIM * DIM];
__device__ __align__(16) __nv_bfloat16 g_T2h[GROUPS][DIM * DIM];
__device__ __align__(16) __nv_bfloat16 g_T2l[GROUPS][DIM * DIM];
__device__ __align__(16) __nv_bfloat16 g_Zh[(size_t)GROUPS * NSAMP * DIM];
__device__ __align__(16) __nv_bfloat16 g_Zl[(size_t)GROUPS * NSAMP * DIM];
__device__ __align__(16) __nv_bfloat16 g_Th[(size_t)GROUPS * DIM * NSAMP];
__device__ __align__(16) __nv_bfloat16 g_Tl[(size_t)GROUPS * DIM * NSAMP];
__device__ float g_normpart[GROUPS][64];
__device__ float g_scale[GROUPS][2];

// ======================= small SIMT kernels =======================
__global__ void colsum_kernel(const float* __restrict__ Z) {
    int g = blockIdx.y, chunk = blockIdx.x, c = threadIdx.x;
    const float* Zg = Z + (size_t)g * NSAMP * DIM;
    size_t base = (size_t)chunk * 512 * DIM + c;
    float s = 0.f;
    #pragma unroll 4
    for (int r = 0; r < 512; r++) s += Zg[base + (size_t)r * DIM];
    g_colsum_part[g][chunk][c] = s;
}

__global__ void mu_kernel() {
    int g = blockIdx.x, c = threadIdx.x;
    float s = 0.f;
    #pragma unroll
    for (int ch = 0; ch < 32; ch++) s += g_colsum_part[g][ch][c];
    g_mu[g][c] = s * (1.0f / NSAMP);
}

// Zc = Z - mu ; bf16 hi/lo split, row-major
__global__ void __launch_bounds__(256) split_kernel(const float* __restrict__ Z) {
    size_t e = ((size_t)blockIdx.x * 256 + threadIdx.x) * 4;
    int g = (int)(e >> 23);
    int d = (int)(e & 511);
    float4 z = *(const float4*)(Z + e);
    float4 m = *(const float4*)&g_mu[g][d];
    float c0 = z.x - m.x, c1 = z.y - m.y, c2 = z.z - m.z, c3 = z.w - m.w;
    __nv_bfloat16 h0 = __float2bfloat16(c0), h1 = __float2bfloat16(c1);
    __nv_bfloat16 h2 = __float2bfloat16(c2), h3 = __float2bfloat16(c3);
    __nv_bfloat16 l0 = __float2bfloat16(c0 - __bfloat162float(h0));
    __nv_bfloat16 l1 = __float2bfloat16(c1 - __bfloat162float(h1));
    __nv_bfloat16 l2 = __float2bfloat16(c2 - __bfloat162float(h2));
    __nv_bfloat16 l3 = __float2bfloat16(c3 - __bfloat162float(h3));
    union { __nv_bfloat16 b[4]; uint2 u; } ph, pl;
    ph.b[0] = h0; ph.b[1] = h1; ph.b[2] = h2; ph.b[3] = h3;
    pl.b[0] = l0; pl.b[1] = l1; pl.b[2] = l2; pl.b[3] = l3;
    *(uint2*)(g_Zh + e) = ph.u;
    *(uint2*)(g_Zl + e) = pl.u;
}

// transpose Zc splits -> ZcT
__global__ void __launch_bounds__(256) transpose_kernel() {
    __shared__ __nv_bfloat16 sh[64][68];
    __shared__ __nv_bfloat16 sl[64][68];
    int g = blockIdx.z;
    int n0 = blockIdx.x * 64, d0 = blockIdx.y * 64;
    int tid = threadIdx.x;
    #pragma unroll
    for (int q = 0; q < 4; q++) {
        int idx = q * 256 + tid;
        int nl = idx >> 4, du = idx & 15;
        size_t goff = ((size_t)g * NSAMP + n0 + nl) * DIM + d0 + du * 4;
        *(uint2*)&sh[nl][du * 4] = *(const uint2*)(g_Zh + goff);
        *(uint2*)&sl[nl][du * 4] = *(const uint2*)(g_Zl + goff);
    }
    __syncthreads();
    #pragma unroll
    for (int q = 0; q < 4; q++) {
        int idx = q * 256 + tid;
        int dl = idx >> 4, nu = idx & 15;
        union { __nv_bfloat16 b[4]; uint2 u; } ph, pl;
        #pragma unroll
        for (int k = 0; k < 4; k++) { ph.b[k] = sh[nu * 4 + k][dl]; pl.b[k] = sl[nu * 4 + k][dl]; }
        size_t toff = ((size_t)g * DIM + d0 + dl) * NSAMP + n0 + nu * 4;
        *(uint2*)(g_Th + toff) = ph.u;
        *(uint2*)(g_Tl + toff) = pl.u;
    }
}

// S = sum of Gram partials + eps I ; Frobenius partials
__global__ void sfin_kernel() {
    int g = blockIdx.y, b = blockIdx.x, t = threadIdx.x;
    float ss = 0.f;
    #pragma unroll
    for (int l = 0; l < 16; l++) {
        int idx = b * 4096 + l * 256 + t;
        int d = idx >> 9, e = idx & 511;
        float v = 0.f;
        #pragma unroll
        for (int s = 0; s < KSPLIT; s++) v += g_Gpart[s][g][idx];
        if (d == e) v += EPS;
        g_Sf[g][idx] = v;
        ss += v * v;
    }
    __shared__ float red[256];
    red[t] = ss; __syncthreads();
    for (int s2 = 128; s2 > 0; s2 >>= 1) {
        if (t < s2) red[t] += red[t + s2];
        __syncthreads();
    }
    if (t == 0) g_normpart[g][b] = red[0];
}

__global__ void norm_kernel() {
    int g = blockIdx.x, t = threadIdx.x;
    __shared__ float red[64];
    red[t] = g_normpart[g][t]; __syncthreads();
    for (int s = 32; s > 0; s >>= 1) {
        if (t < s) red[t] += red[t + s];
        __syncthreads();
    }
    if (t == 0) {
        float nrm = sqrtf(red[0]);
        g_scale[g][0] = 1.0f / nrm;
        g_scale[g][1] = rsqrtf(nrm);
    }
}

__global__ void nsinit_kernel() {
    int idx = blockIdx.x * 1024 + threadIdx.x;
    int g = idx >> 18;
    int r = idx & 262143;
    int d = r >> 9, e = r & 511;
    float sv = g_Sf[g][r] * g_scale[g][0];
    __nv_bfloat16 sh = __float2bfloat16(sv);
    g_Sh[g][r] = sh;
    g_Sl[g][r] = __float2bfloat16(sv - __bfloat162float(sh));
    float b = (d == e ? 1.5f : 0.0f) - 0.5f * sv;
    g_Bf[0][g][r] = b;
    __nv_bfloat16 bh = __float2bfloat16(b);
    g_Bh[0][g][r] = bh;
    g_Bl[0][g][r] = __float2bfloat16(b - __bfloat162float(bh));
}

// ======================= HMMA GEMM (mma.sync bf16-split) =======================
// C[i][j] = sum_k A[i][k]*B[j][k], split emu: Ah*Bh + Ah*Bl + Al*Bh, f32 acc.
// MODE 0: Gram partial -> g_Gpart[s][g] (fp32, mirror if sym)
// MODE 1: Ch/Cl = split(acc)
// MODE 2: v = 1.5*Dm - 0.5*acc -> Cf + Ch/Cl
// MODE 3: Cf = scale * acc (final output)
template<int MODE, int BN>
__global__ void __launch_bounds__(256) mma_gemm(
    const __nv_bfloat16* __restrict__ Ah, const __nv_bfloat16* __restrict__ Al,
    const __nv_bfloat16* __restrict__ Bh, const __nv_bfloat16* __restrict__ Bl,
    size_t aStride, size_t bStride, int K, int ksplit,
    float* __restrict__ Cf, __nv_bfloat16* __restrict__ Ch, __nv_bfloat16* __restrict__ Cl,
    const float* __restrict__ Dm, int sym)
{
    constexpr int NF = BN / 32;          // n-frags per warp
    constexpr int QB = BN / 64;          // B-tile load rounds
    constexpr int AT = 128 * 40;         // A tile halves (padded stride 40)
    constexpr int BT = BN * 40;
    constexpr int BUFH = 2 * AT + 2 * BT;

    int zz = blockIdx.z;
    int g = zz / ksplit, s = zz % ksplit;
    int it = blockIdx.y, jt = blockIdx.x;
    if (sym && jt < it) return;
    int i0 = it * 128, j0 = jt * BN;
    int Ks = K / ksplit, kBase = s * Ks;
    int nch = Ks >> 5;
    int K8 = K >> 3;

    const uint4* Ahg = (const uint4*)(Ah + g * aStride + (size_t)i0 * K + kBase);
    const uint4* Alg = (const uint4*)(Al + g * aStride + (size_t)i0 * K + kBase);
    const uint4* Bhg = (const uint4*)(Bh + g * bStride + (size_t)j0 * K + kBase);
    const uint4* Blg = (const uint4*)(Bl + g * bStride + (size_t)j0 * K + kBase);

    extern __shared__ char smem[];
    uint32_t sb = smem_to_u32(smem);
    int tid = threadIdx.x;
    int lane = tid & 31, warp = tid >> 5;
    int wm = warp >> 2, wn = warp & 3;

    // ldmatrix per-thread addresses (bytes)
    int q4 = lane >> 3, lr = lane & 7;
    uint32_t aAddr = sb + (uint32_t)(((wm * 64 + lr + (q4 & 1) * 8) * 40 + (q4 >> 1) * 8) * 2);
    int bl2 = lane & 15;
    uint32_t bAddr = sb + (uint32_t)(((wn * (BN / 4) + (bl2 & 7)) * 40 + ((bl2 >> 3) * 8)) * 2)
                   + (uint32_t)(2 * AT * 2);

    float acc[4][NF][4];
    #pragma unroll
    for (int mf = 0; mf < 4; mf++)
        #pragma unroll
        for (int nf = 0; nf < NF; nf++)
            #pragma unroll
            for (int v = 0; v < 4; v++) acc[mf][nf][v] = 0.f;

    uint4 stage[4 + 2 * QB];

    auto loadRegs = [&](int c) {
        #pragma unroll
        for (int t = 0; t < 2; t++) {
            const uint4* src = t ? Alg : Ahg;
            #pragma unroll
            for (int r = 0; r < 2; r++) {
                int idx = r * 256 + tid;
                int row = idx >> 2, seg = idx & 3;
                stage[t * 2 + r] = src[(size_t)row * K8 + c * 4 + seg];
            }
        }
        #pragma unroll
        for (int t = 0; t < 2; t++) {
            const uint4* src = t ? Blg : Bhg;
            #pragma unroll
            for (int r = 0; r < QB; r++) {
                int idx = r * 256 + tid;
                int row = idx >> 2, seg = idx & 3;
                stage[4 + t * QB + r] = src[(size_t)row * K8 + c * 4 + seg];
            }
        }
    };
    auto stsRegs = [&](int buf) {
        uint32_t bB = sb + (uint32_t)(buf * BUFH * 2);
        #pragma unroll
        for (int t = 0; t < 2; t++)
            #pragma unroll
            for (int r = 0; r < 2; r++) {
                int idx = r * 256 + tid;
                int row = idx >> 2, seg = idx & 3;
                uint4 v = stage[t * 2 + r];
                STS128(v.x, v.y, v.z, v.w, bB + (uint32_t)((t * AT + row * 40 + seg * 8) * 2));
            }
        #pragma unroll
        for (int t = 0; t < 2; t++)
            #pragma unroll
            for (int r = 0; r < QB; r++) {
                int idx = r * 256 + tid;
                int row = idx >> 2, seg = idx & 3;
                uint4 v = stage[4 + t * QB + r];
                STS128(v.x, v.y, v.z, v.w, bB + (uint32_t)((2 * AT + t * BT + row * 40 + seg * 8) * 2));
            }
    };

    loadRegs(0);
    stsRegs(0);
    __syncthreads();

    for (int c = 0; c < nch; c++) {
        int buf = c & 1;
        if (c + 1 < nch) loadRegs(c + 1);

        uint32_t bB = (uint32_t)(buf * BUFH * 2);
        #pragma unroll
        for (int k16 = 0; k16 < 2; k16++) {
            uint32_t bhF[NF][2], blF[NF][2];
            #pragma unroll
            for (int nf = 0; nf < NF; nf++) {
                uint32_t ad = bAddr + bB + (uint32_t)((nf * 8 * 40 + k16 * 16) * 2);
                LDSM_X2(bhF[nf][0], bhF[nf][1], ad);
                LDSM_X2(blF[nf][0], blF[nf][1], ad + (uint32_t)(BT * 2));
            }
            #pragma unroll
            for (int mf = 0; mf < 4; mf++) {
                uint32_t ad = aAddr + bB + (uint32_t)((mf * 16 * 40 + k16 * 16) * 2);
                uint32_t ah[4], al[4];
                LDSM_X4(ah[0], ah[1], ah[2], ah[3], ad);
                LDSM_X4(al[0], al[1], al[2], al[3], ad + (uint32_t)(AT * 2));
                #pragma unroll
                for (int nf = 0; nf < NF; nf++) {
                    MMA16816(acc[mf][nf], ah, bhF[nf]);
                    MMA16816(acc[mf][nf], ah, blF[nf]);
                    MMA16816(acc[mf][nf], al, bhF[nf]);
                }
            }
        }
        if (c + 1 < nch) stsRegs(buf ^ 1);
        __syncthreads();
    }

    // ---------------- epilogue ----------------
    const size_t DDl = (size_t)DIM * DIM;
    int r0 = i0 + wm * 64 + (lane >> 2);
    int jc = j0 + wn * (BN / 4) + (lane & 3) * 2;

    if (MODE == 0) {
        float* Cout = Cf + ((size_t)(s * GROUPS + g)) * DDl;
        #pragma unroll
        for (int mf = 0; mf < 4; mf++)
            #pragma unroll
            for (int nf = 0; nf < NF; nf++) {
                int r = r0 + mf * 16, j = jc + nf * 8;
                float* a = acc[mf][nf];
                *(float2*)&Cout[(size_t)r * DIM + j]       = make_float2(a[0], a[1]);
                *(float2*)&Cout[(size_t)(r + 8) * DIM + j] = make_float2(a[2], a[3]);
                if (sym && it != jt) {
                    Cout[(size_t)j * DIM + r]           = a[0];
                    Cout[(size_t)(j + 1) * DIM + r]     = a[1];
                    Cout[(size_t)j * DIM + r + 8]       = a[2];
                    Cout[(size_t)(j + 1) * DIM + r + 8] = a[3];
                }
            }
    } else if (MODE == 1 || MODE == 2) {
        size_t base = (size_t)g * DDl;
        #pragma unroll
        for (int mf = 0; mf < 4; mf++)
            #pragma unroll
            for (int nf = 0; nf < NF; nf++) {
                int r = r0 + mf * 16, j = jc + nf * 8;
                float* a = acc[mf][nf];
                #pragma unroll
                for (int e = 0; e < 4; e++) {
                    int rr = r + (e >> 1) * 8, jj = j + (e & 1);
                    size_t o = base + (size_t)rr * DIM + jj;
                    float v = a[e];
                    if (MODE == 2) v = 1.5f * Dm[o] - 0.5f * v;
                    __nv_bfloat16 h = __float2bfloat16(v);
                    __nv_bfloat16 l = __float2bfloat16(v - __bfloat162float(h));
                    if (MODE == 2) Cf[o] = v;
                    Ch[o] = h; Cl[o] = l;
                }
            }
    } else {
        float scl = g_scale[g][1];
        float* Cout = Cf + (size_t)g * ((size_t)NSAMP * DIM);
        #pragma unroll
        for (int mf = 0; mf < 4; mf++)
            #pragma unroll
            for (int nf = 0; nf < NF; nf++) {
                int r = r0 + mf * 16, j = jc + nf * 8;
                float* a = acc[mf][nf];
                *(float2*)&Cout[(size_t)r * DIM + j]       = make_float2(scl * a[0], scl * a[1]);
                *(float2*)&Cout[(size_t)(r + 8) * DIM + j] = make_float2(scl * a[2], scl * a[3]);
            }
    }
}

// ======================= launch =======================
#define SMEM_128 ((2 * (2 * 128 * 40 + 2 * 128 * 40)) * 2)   // 81920 B
#define SMEM_64  ((2 * (2 * 128 * 40 + 2 * 64 * 40)) * 2)    // 61440 B

extern "C" void kernel_launch(void* const* d_in, const int* in_sizes, int n_in,
                              void* d_out, int out_size) {
    (void)in_sizes; (void)n_in; (void)out_size;
    const float* in = (const float*)d_in[0];
    float* out = (float*)d_out;

    __nv_bfloat16 *Zh, *Zl, *Th, *Tl, *Sh, *Sl, *Bh, *Bl, *T1h, *T1l, *T2h, *T2l;
    float *Sf, *Bf, *Gp;
    cudaGetSymbolAddress((void**)&Zh, g_Zh);
    cudaGetSymbolAddress((void**)&Zl, g_Zl);
    cudaGetSymbolAddress((void**)&Th, g_Th);
    cudaGetSymbolAddress((void**)&Tl, g_Tl);
    cudaGetSymbolAddress((void**)&Sh, g_Sh);
    cudaGetSymbolAddress((void**)&Sl, g_Sl);
    cudaGetSymbolAddress((void**)&Bh, g_Bh);
    cudaGetSymbolAddress((void**)&Bl, g_Bl);
    cudaGetSymbolAddress((void**)&T1h, g_T1h);
    cudaGetSymbolAddress((void**)&T1l, g_T1l);
    cudaGetSymbolAddress((void**)&T2h, g_T2h);
    cudaGetSymbolAddress((void**)&T2l, g_T2l);
    cudaGetSymbolAddress((void**)&Sf, g_Sf);
    cudaGetSymbolAddress((void**)&Bf, g_Bf);
    cudaGetSymbolAddress((void**)&Gp, g_Gpart);

    cudaFuncSetAttribute((const void*)mma_gemm<0, 128>, cudaFuncAttributeMaxDynamicSharedMemorySize, SMEM_128);
    cudaFuncSetAttribute((const void*)mma_gemm<1, 64>,  cudaFuncAttributeMaxDynamicSharedMemorySize, SMEM_64);
    cudaFuncSetAttribute((const void*)mma_gemm<2, 64>,  cudaFuncAttributeMaxDynamicSharedMemorySize, SMEM_64);
    cudaFuncSetAttribute((const void*)mma_gemm<3, 128>, cudaFuncAttributeMaxDynamicSharedMemorySize, SMEM_128);

    const size_t DD = (size_t)DIM * DIM;
    const size_t GD = (size_t)GROUPS * DD;
    const size_t ZS = (size_t)NSAMP * DIM;
    const size_t TS = (size_t)DIM * NSAMP;

    colsum_kernel<<<dim3(32, GROUPS), 512>>>(in);
    mu_kernel<<<GROUPS, 512>>>();
    split_kernel<<<32768, 256>>>(in);
    transpose_kernel<<<dim3(256, 8, GROUPS), 256>>>();

    // Gram partials: S_s = Zc^T Zc over k-slab s (K-split x8 for occupancy)
    mma_gemm<0, 128><<<dim3(4, 4, GROUPS * KSPLIT), 256, SMEM_128>>>(
        Th, Tl, Th, Tl, TS, TS, NSAMP, KSPLIT, Gp, nullptr, nullptr, nullptr, 1);
    sfin_kernel<<<dim3(64, GROUPS), 256>>>();
    norm_kernel<<<GROUPS, 64>>>();
    nsinit_kernel<<<1024, 1024>>>();

    int cur = 0;
    for (int itr = 0; itr < 4; itr++) {
        int nxt = cur ^ 1;
        mma_gemm<1, 64><<<dim3(8, 4, GROUPS), 256, SMEM_64>>>(
            Bh + cur * GD, Bl + cur * GD, Bh + cur * GD, Bl + cur * GD,
            DD, DD, DIM, 1, nullptr, T1h, T1l, nullptr, 0);
        mma_gemm<1, 64><<<dim3(8, 4, GROUPS), 256, SMEM_64>>>(
            T1h, T1l, Bh + cur * GD, Bl + cur * GD,
            DD, DD, DIM, 1, nullptr, T2h, T2l, nullptr, 0);
        mma_gemm<2, 64><<<dim3(8, 4, GROUPS), 256, SMEM_64>>>(
            T2h, T2l, Sh, Sl,
            DD, DD, DIM, 1, Bf + nxt * GD, Bh + nxt * GD, Bl + nxt * GD,
            Bf + cur * GD, 0);
        cur = nxt;
    }

    // out = (1/sqrt(||S||)) * Zc * B^T
    mma_gemm<3, 128><<<dim3(4, 128, GROUPS), 256, SMEM_128>>>(
        Zh, Zl, Bh + cur * GD, Bl + cur * GD,
        ZS, DD, DIM, 1, out, nullptr, nullptr, nullptr, 0);
}